// round 14
// baseline (speedup 1.0000x reference)
#include <cuda_runtime.h>
#include <cuda_fp16.h>
#include <cstdint>

constexpr int DIMC = 64;
constexpr int D_ = 64, H_ = 128, W_ = 128;
constexpr int HW_ = H_ * W_;
constexpr size_t NSP = (size_t)D_ * HW_;
constexpr int KTOT = 3 * DIMC;
constexpr float EPS_ = 1e-5f;
constexpr float SLOPE_ = 0.01f;

__device__ __align__(16) __half g_scrh[(size_t)KTOT * NSP];   // 384 MB branch scratch [k][spatial]
__device__ __align__(16) __half g_outh[(size_t)DIMC * NSP];   // 128 MB pre-norm output [c][spatial]
__device__ __align__(16) __half g_wh[KTOT * 64];              // fp16 weights [k][n]
__device__ float g_sum[KTOT];
__device__ float g_sq[KTOT];
__device__ __align__(8) float2 g_sb[KTOT];                    // packed (scale, bias)
__device__ float g_osum[DIMC];
__device__ float g_osq[DIMC];
__device__ float g_oscale[DIMC];
__device__ float g_obias[DIMC];

__device__ __forceinline__ float warp_red(float v) {
    #pragma unroll
    for (int o = 16; o > 0; o >>= 1) v += __shfl_down_sync(0xffffffffu, v, o);
    return v;
}

__device__ __forceinline__ uint32_t smem_to_u32(const void* p) {
    uint32_t a;
    asm("{ .reg .u64 t; cvta.to.shared.u64 t, %1; cvt.u32.u64 %0, t; }" : "=r"(a) : "l"(p));
    return a;
}

__device__ __forceinline__ void ldmx4t(uint32_t* r, uint32_t addr) {
    asm volatile("ldmatrix.sync.aligned.m8n8.x4.trans.shared.b16 {%0,%1,%2,%3}, [%4];"
                 : "=r"(r[0]), "=r"(r[1]), "=r"(r[2]), "=r"(r[3]) : "r"(addr));
}

__device__ __forceinline__ void mma16816(float* d, const uint32_t* a, uint32_t b0, uint32_t b1) {
    asm volatile("mma.sync.aligned.m16n8k16.row.col.f32.f16.f16.f32 "
                 "{%0,%1,%2,%3}, {%4,%5,%6,%7}, {%8,%9}, {%0,%1,%2,%3};"
                 : "+f"(d[0]), "+f"(d[1]), "+f"(d[2]), "+f"(d[3])
                 : "r"(a[0]), "r"(a[1]), "r"(a[2]), "r"(a[3]), "r"(b0), "r"(b1));
}

__global__ void k_prep(const float* __restrict__ wpw) {
    int t = threadIdx.x;
    if (t < KTOT) { g_sum[t] = 0.f; g_sq[t] = 0.f; }
    if (t < DIMC) { g_osum[t] = 0.f; g_osq[t] = 0.f; }
    for (int idx = t; idx < 64 * KTOT; idx += 256) {
        int k = idx >> 6, n = idx & 63;
        g_wh[idx] = __float2half(wpw[n * KTOT + k]);
    }
}

// Fused 3-branch depthwise conv (+bias) + fp32 stats, fp16 scratch stores.
// Thread computes an h-pair (rows h, h+1) x 4 w: shared rows loaded once.
__global__ void __launch_bounds__(128) k_conv(
    const float* __restrict__ x,
    const float* __restrict__ wd, const float* __restrict__ bd,
    const float* __restrict__ wh, const float* __restrict__ bh,
    const float* __restrict__ wv, const float* __restrict__ bw)
{
    const int d = blockIdx.x;
    const int c = blockIdx.y;

    float Wd[9], Wh[9], Wv[9];
    #pragma unroll
    for (int i = 0; i < 9; i++) {
        Wd[i] = wd[c * 9 + i];
        Wh[i] = wh[c * 9 + i];
        Wv[i] = wv[c * 9 + i];
    }
    const float bdv = bd[c], bhv = bh[c], bwv = bw[c];

    const float* pc = x + (size_t)c * NSP + (size_t)d * HW_;
    const float* pm = pc - HW_;
    const float* pq = pc + HW_;
    const bool dm = d > 0, dp = d < D_ - 1;

    __half* od = g_scrh + (size_t)c * NSP + (size_t)d * HW_;
    __half* oh = od + (size_t)DIMC * NSP;
    __half* ow = oh + (size_t)DIMC * NSP;

    float s0 = 0.f, q0 = 0.f, s1 = 0.f, q1 = 0.f, s2 = 0.f, q2 = 0.f;

    for (int it = threadIdx.x; it < (HW_ >> 3); it += 128) {
        const int h = (it >> 5) * 2;
        const int w4 = (it & 31) << 2;
        const bool wl = w4 > 0, wr = w4 < W_ - 4;
        const bool vhm = h > 0;
        const bool vhp2 = (h + 2) < H_;

        auto ld6 = [&](float* a, const float* row, bool valid) {
            if (valid) {
                float4 f = *reinterpret_cast<const float4*>(row + w4);
                a[1] = f.x; a[2] = f.y; a[3] = f.z; a[4] = f.w;
                a[0] = wl ? row[w4 - 1] : 0.f;
                a[5] = wr ? row[w4 + 4] : 0.f;
            } else {
                a[0] = a[1] = a[2] = a[3] = a[4] = a[5] = 0.f;
            }
        };
        auto ld4 = [&](float* a, const float* row, bool valid) {
            if (valid) {
                float4 f = *reinterpret_cast<const float4*>(row + w4);
                a[0] = f.x; a[1] = f.y; a[2] = f.z; a[3] = f.w;
            } else {
                a[0] = a[1] = a[2] = a[3] = 0.f;
            }
        };

        float pc6[4][6];
        ld6(pc6[0], pc + (h - 1) * W_, vhm);
        ld6(pc6[1], pc + h * W_, true);
        ld6(pc6[2], pc + (h + 1) * W_, true);
        ld6(pc6[3], pc + (h + 2) * W_, vhp2);
        float pm6a[6], pm6b[6], pm4a[4], pm4b[4];
        ld6(pm6a, pm + h * W_, dm);
        ld6(pm6b, pm + (h + 1) * W_, dm);
        ld4(pm4a, pm + (h - 1) * W_, dm && vhm);
        ld4(pm4b, pm + (h + 2) * W_, dm && vhp2);
        float pq6a[6], pq6b[6], pq4a[4], pq4b[4];
        ld6(pq6a, pq + h * W_, dp);
        ld6(pq6b, pq + (h + 1) * W_, dp);
        ld4(pq4a, pq + (h - 1) * W_, dp && vhm);
        ld4(pq4b, pq + (h + 2) * W_, dp && vhp2);

        auto comp = [&](const float (&cm)[6], const float (&cc6)[6], const float (&cp)[6],
                        const float (&mm6)[6], const float (&pp6)[6],
                        const float (&mhm)[4], const float (&mhp)[4],
                        const float (&phm)[4], const float (&php)[4], int idx) {
            float rd[4], rh[4], rw[4];
            #pragma unroll
            for (int i = 0; i < 4; i++) {
                float vd = bdv;
                vd = fmaf(Wd[0], cm[i], vd);  vd = fmaf(Wd[1], cm[i+1], vd);  vd = fmaf(Wd[2], cm[i+2], vd);
                vd = fmaf(Wd[3], cc6[i], vd); vd = fmaf(Wd[4], cc6[i+1], vd); vd = fmaf(Wd[5], cc6[i+2], vd);
                vd = fmaf(Wd[6], cp[i], vd);  vd = fmaf(Wd[7], cp[i+1], vd);  vd = fmaf(Wd[8], cp[i+2], vd);

                float vh = bhv;
                vh = fmaf(Wh[0], mm6[i], vh); vh = fmaf(Wh[1], mm6[i+1], vh); vh = fmaf(Wh[2], mm6[i+2], vh);
                vh = fmaf(Wh[3], cc6[i], vh); vh = fmaf(Wh[4], cc6[i+1], vh); vh = fmaf(Wh[5], cc6[i+2], vh);
                vh = fmaf(Wh[6], pp6[i], vh); vh = fmaf(Wh[7], pp6[i+1], vh); vh = fmaf(Wh[8], pp6[i+2], vh);

                float vw = bwv;
                vw = fmaf(Wv[0], mhm[i], vw);   vw = fmaf(Wv[1], mm6[i+1], vw); vw = fmaf(Wv[2], mhp[i], vw);
                vw = fmaf(Wv[3], cm[i+1], vw);  vw = fmaf(Wv[4], cc6[i+1], vw); vw = fmaf(Wv[5], cp[i+1], vw);
                vw = fmaf(Wv[6], phm[i], vw);   vw = fmaf(Wv[7], pp6[i+1], vw); vw = fmaf(Wv[8], php[i], vw);

                rd[i] = vd; rh[i] = vh; rw[i] = vw;
                s0 += vd; q0 = fmaf(vd, vd, q0);
                s1 += vh; q1 = fmaf(vh, vh, q1);
                s2 += vw; q2 = fmaf(vw, vw, q2);
            }
            __half2 a0 = __floats2half2_rn(rd[0], rd[1]);
            __half2 a1 = __floats2half2_rn(rd[2], rd[3]);
            __half2 b0 = __floats2half2_rn(rh[0], rh[1]);
            __half2 b1 = __floats2half2_rn(rh[2], rh[3]);
            __half2 c0 = __floats2half2_rn(rw[0], rw[1]);
            __half2 c1 = __floats2half2_rn(rw[2], rw[3]);
            *reinterpret_cast<uint2*>(od + idx) =
                make_uint2(*reinterpret_cast<unsigned*>(&a0), *reinterpret_cast<unsigned*>(&a1));
            *reinterpret_cast<uint2*>(oh + idx) =
                make_uint2(*reinterpret_cast<unsigned*>(&b0), *reinterpret_cast<unsigned*>(&b1));
            *reinterpret_cast<uint2*>(ow + idx) =
                make_uint2(*reinterpret_cast<unsigned*>(&c0), *reinterpret_cast<unsigned*>(&c1));
        };

        float mhpA[4] = { pm6b[1], pm6b[2], pm6b[3], pm6b[4] };
        float phpA[4] = { pq6b[1], pq6b[2], pq6b[3], pq6b[4] };
        float mhmB[4] = { pm6a[1], pm6a[2], pm6a[3], pm6a[4] };
        float phmB[4] = { pq6a[1], pq6a[2], pq6a[3], pq6a[4] };

        comp(pc6[0], pc6[1], pc6[2], pm6a, pq6a, pm4a, mhpA, pq4a, phpA, h * W_ + w4);
        comp(pc6[1], pc6[2], pc6[3], pm6b, pq6b, mhmB, pm4b, phmB, pq4b, (h + 1) * W_ + w4);
    }

    s0 = warp_red(s0); q0 = warp_red(q0);
    s1 = warp_red(s1); q1 = warp_red(q1);
    s2 = warp_red(s2); q2 = warp_red(q2);
    if ((threadIdx.x & 31) == 0) {
        atomicAdd(&g_sum[c], s0);             atomicAdd(&g_sq[c], q0);
        atomicAdd(&g_sum[DIMC + c], s1);      atomicAdd(&g_sq[DIMC + c], q1);
        atomicAdd(&g_sum[2 * DIMC + c], s2);  atomicAdd(&g_sq[2 * DIMC + c], q2);
    }
}

__global__ void k_stats() {
    int k = threadIdx.x;
    if (k >= KTOT) return;
    const float n = (float)NSP;
    float mean = g_sum[k] / n;
    float var = g_sq[k] / n - mean * mean;
    float sc = rsqrtf(var + EPS_);
    g_sb[k] = make_float2(sc, -mean * sc);
}

// ---------- mma.sync pointwise GEMM ----------
// 128 threads (4 warps = 2 m-groups x 2 n-halves), warp tile m64 x n32.
// Full K=192 resident (swizzled A 48KB + B 24KB = 72KB -> 3 CTAs/SM).
// Bigger warp tile: 6 LDSM per 16 MMAs (vs 4 per 8) -> ~25% less L1 traffic.
constexpr int PW_SM_B = 0;                       // 192 * 128 = 24576
constexpr int PW_SM_A = 24576;                   // 192 * 256 = 49152 (reused: staging)
constexpr int PW_SM_TOTAL = 73728;               // 9 x 8KB -> 3 CTAs/SM
constexpr int STG_STRIDE = 136;                  // halves per channel row in staging

__device__ __forceinline__ int a_off(int k, int byte) {
    return PW_SM_A + k * 256 + (byte ^ ((k & 7) << 4));
}
__device__ __forceinline__ int b_off(int k, int byte) {
    return PW_SM_B + k * 128 + (byte ^ ((k & 7) << 4));
}

__global__ void __launch_bounds__(128, 3) k_pw_mma() {
    extern __shared__ char smem[];
    const uint32_t sa = smem_to_u32(smem);
    const int tid = threadIdx.x;
    const int wid = tid >> 5;
    const int lid = tid & 31;
    const size_t base = (size_t)blockIdx.x * 128;

    // B fill: 192 rows x 128B, swizzled 16B chunks
    {
        const uint4* src = reinterpret_cast<const uint4*>(g_wh);
        for (int i = tid; i < KTOT * 8; i += 128) {
            int row = i >> 3, part = i & 7;
            *reinterpret_cast<uint4*>(smem + b_off(row, part * 16)) = src[i];
        }
    }

    // A fill: normalize+lrelu fp16 scratch into swizzled rows
    #pragma unroll
    for (int it = 0; it < 24; it++) {
        const int idx = it * 128 + tid;
        const int g = idx & 15;
        const int k = idx >> 4;
        uint4 raw = *reinterpret_cast<const uint4*>(g_scrh + (size_t)k * NSP + base + g * 8);
        float2 s = __ldg(&g_sb[k]);
        const __half2* hp = reinterpret_cast<const __half2*>(&raw);
        uint4 outv;
        uint32_t* ov = reinterpret_cast<uint32_t*>(&outv);
        #pragma unroll
        for (int q = 0; q < 4; q++) {
            float2 f = __half22float2(hp[q]);
            float v0 = fmaf(f.x, s.x, s.y); v0 = fmaxf(v0, SLOPE_ * v0);
            float v1 = fmaf(f.y, s.x, s.y); v1 = fmaxf(v1, SLOPE_ * v1);
            __half2 h = __floats2half2_rn(v0, v1);
            ov[q] = *reinterpret_cast<uint32_t*>(&h);
        }
        *reinterpret_cast<uint4*>(smem + a_off(k, g * 16)) = outv;
    }
    __syncthreads();

    // warp tile: m0 = (wid&1)*64 (4 m16 tiles), n-half = (wid>>1)*32
    const int m0 = (wid & 1) * 64;
    const int nh = (wid >> 1) * 32;

    float acc[4][4][4];
    #pragma unroll
    for (int mt = 0; mt < 4; mt++)
        #pragma unroll
        for (int nt = 0; nt < 4; nt++)
            #pragma unroll
            for (int e = 0; e < 4; e++) acc[mt][nt][e] = 0.f;

    const int a_k = (lid & 7) | ((lid & 16) >> 1);
    const int a_m = (lid & 8);
    const int b_k = lid & 15;
    const int b_n = (lid >> 4) * 8;

    #pragma unroll
    for (int ks = 0; ks < 12; ks++) {
        const int k0 = ks * 16;
        uint32_t bf[2][4];
        #pragma unroll
        for (int nb = 0; nb < 2; nb++)
            ldmx4t(bf[nb], sa + b_off(k0 + b_k, (nh + nb * 16 + b_n) * 2));
        #pragma unroll
        for (int mt = 0; mt < 4; mt++) {
            uint32_t af[4];
            ldmx4t(af, sa + a_off(k0 + a_k, (m0 + mt * 16 + a_m) * 2));
            #pragma unroll
            for (int nb = 0; nb < 2; nb++) {
                mma16816(acc[mt][2 * nb],     af, bf[nb][0], bf[nb][1]);
                mma16816(acc[mt][2 * nb + 1], af, bf[nb][2], bf[nb][3]);
            }
        }
    }
    __syncthreads();  // everyone done with A and B regions

    // reduction buffer lives in the dead B region
    float* red = reinterpret_cast<float*>(smem + PW_SM_B);
    if (tid < 128) red[tid] = 0.f;
    __syncthreads();

    const int r_lo = (lid >> 2);
    const int c_off = (lid & 3) * 2;
    float sc0[4], qc0[4], sc1[4], qc1[4];
    #pragma unroll
    for (int nt = 0; nt < 4; nt++) { sc0[nt] = qc0[nt] = sc1[nt] = qc1[nt] = 0.f; }
    #pragma unroll
    for (int mt = 0; mt < 4; mt++)
        #pragma unroll
        for (int nt = 0; nt < 4; nt++) {
            float d0 = acc[mt][nt][0], d1 = acc[mt][nt][1];
            float d2 = acc[mt][nt][2], d3 = acc[mt][nt][3];
            sc0[nt] += d0 + d2; qc0[nt] += d0 * d0 + d2 * d2;
            sc1[nt] += d1 + d3; qc1[nt] += d1 * d1 + d3 * d3;
        }
    #pragma unroll
    for (int o = 4; o <= 16; o <<= 1) {
        #pragma unroll
        for (int nt = 0; nt < 4; nt++) {
            sc0[nt] += __shfl_xor_sync(0xffffffffu, sc0[nt], o);
            qc0[nt] += __shfl_xor_sync(0xffffffffu, qc0[nt], o);
            sc1[nt] += __shfl_xor_sync(0xffffffffu, sc1[nt], o);
            qc1[nt] += __shfl_xor_sync(0xffffffffu, qc1[nt], o);
        }
    }
    if (lid < 4) {
        #pragma unroll
        for (int nt = 0; nt < 4; nt++) {
            const int c0 = nh + nt * 8 + c_off;
            atomicAdd(&red[c0], sc0[nt]);
            atomicAdd(&red[64 + c0], qc0[nt]);
            atomicAdd(&red[c0 + 1], sc1[nt]);
            atomicAdd(&red[64 + c0 + 1], qc1[nt]);
        }
    }

    // stage accumulators (fp16) into the dead A region
    __half* stg = reinterpret_cast<__half*>(smem + PW_SM_A);
    #pragma unroll
    for (int mt = 0; mt < 4; mt++) {
        const int row = m0 + mt * 16 + r_lo;
        #pragma unroll
        for (int nt = 0; nt < 4; nt++) {
            const int c0 = nh + nt * 8 + c_off;
            stg[c0 * STG_STRIDE + row]           = __float2half(acc[mt][nt][0]);
            stg[(c0 + 1) * STG_STRIDE + row]     = __float2half(acc[mt][nt][1]);
            stg[c0 * STG_STRIDE + row + 8]       = __float2half(acc[mt][nt][2]);
            stg[(c0 + 1) * STG_STRIDE + row + 8] = __float2half(acc[mt][nt][3]);
        }
    }
    __syncthreads();

    if (tid < 64) atomicAdd(&g_osum[tid], red[tid]);
    else atomicAdd(&g_osq[tid - 64], red[tid]);

    {
        const int c = tid >> 1;
        const int seg = (tid & 1) * 64;
        const uint4* src = reinterpret_cast<const uint4*>(stg + c * STG_STRIDE + seg);
        uint4* dst = reinterpret_cast<uint4*>(g_outh + (size_t)c * NSP + base + seg);
        #pragma unroll
        for (int i = 0; i < 8; i++) dst[i] = src[i];
    }
}

__global__ void k_ofin() {
    int c = threadIdx.x;
    if (c >= DIMC) return;
    const float n = (float)NSP;
    float mean = g_osum[c] / n;
    float var = g_osq[c] / n - mean * mean;
    float sc = rsqrtf(var + EPS_);
    g_oscale[c] = sc;
    g_obias[c] = -mean * sc;
}

__global__ void __launch_bounds__(256) k_onorm(float* __restrict__ out) {
    const int c = blockIdx.y;
    const size_t pos = ((size_t)blockIdx.x * 256 + threadIdx.x) * 8;
    uint4 raw = *reinterpret_cast<const uint4*>(g_outh + (size_t)c * NSP + pos);
    const float sc = g_oscale[c], bi = g_obias[c];
    const __half2* hp = reinterpret_cast<const __half2*>(&raw);
    float o[8];
    #pragma unroll
    for (int q = 0; q < 4; q++) {
        float2 f = __half22float2(hp[q]);
        float v0 = fmaf(f.x, sc, bi); v0 = fmaxf(v0, SLOPE_ * v0);
        float v1 = fmaf(f.y, sc, bi); v1 = fmaxf(v1, SLOPE_ * v1);
        o[2 * q] = v0; o[2 * q + 1] = v1;
    }
    float4* dst = reinterpret_cast<float4*>(out + (size_t)c * NSP + pos);
    dst[0] = make_float4(o[0], o[1], o[2], o[3]);
    dst[1] = make_float4(o[4], o[5], o[6], o[7]);
}

extern "C" void kernel_launch(void* const* d_in, const int* in_sizes, int n_in,
                              void* d_out, int out_size) {
    const float* x   = (const float*)d_in[0];
    const float* wd  = (const float*)d_in[1];
    const float* bd  = (const float*)d_in[2];
    const float* wh  = (const float*)d_in[3];
    const float* bh  = (const float*)d_in[4];
    const float* wv  = (const float*)d_in[5];
    const float* bw  = (const float*)d_in[6];
    const float* wpw = (const float*)d_in[7];
    // d_in[8] = pointwise bias: dropped (cancels exactly in the output InstanceNorm)
    float* out = (float*)d_out;

    cudaFuncSetAttribute(k_pw_mma, cudaFuncAttributeMaxDynamicSharedMemorySize, PW_SM_TOTAL);

    k_prep<<<1, 256>>>(wpw);
    k_conv<<<dim3(D_, DIMC), 128>>>(x, wd, bd, wh, bh, wv, bw);
    k_stats<<<1, KTOT>>>();
    k_pw_mma<<<(unsigned)(NSP / 128), 128, PW_SM_TOTAL>>>();
    k_ofin<<<1, DIMC>>>();
    k_onorm<<<dim3((unsigned)(NSP / 2048), DIMC), 256>>>(out);
}

// round 15
// speedup vs baseline: 1.0091x; 1.0091x over previous
#include <cuda_runtime.h>
#include <cuda_fp16.h>
#include <cstdint>

constexpr int DIMC = 64;
constexpr int D_ = 64, H_ = 128, W_ = 128;
constexpr int HW_ = H_ * W_;
constexpr size_t NSP = (size_t)D_ * HW_;
constexpr int KTOT = 3 * DIMC;
constexpr float EPS_ = 1e-5f;
constexpr float SLOPE_ = 0.01f;

__device__ __align__(16) __half g_scrh[(size_t)KTOT * NSP];   // 384 MB branch scratch [k][spatial]
__device__ __align__(16) __half g_outh[(size_t)DIMC * NSP];   // 128 MB pre-norm output [c][spatial]
__device__ __align__(16) __half g_wh[KTOT * 64];              // fp16 weights [k][n]
__device__ float g_sum[KTOT];
__device__ float g_sq[KTOT];
__device__ __align__(8) float2 g_sb[KTOT];                    // packed (scale, bias)
__device__ float g_osum[DIMC];
__device__ float g_osq[DIMC];
__device__ float g_oscale[DIMC];
__device__ float g_obias[DIMC];

__device__ __forceinline__ float warp_red(float v) {
    #pragma unroll
    for (int o = 16; o > 0; o >>= 1) v += __shfl_down_sync(0xffffffffu, v, o);
    return v;
}

__device__ __forceinline__ uint32_t smem_to_u32(const void* p) {
    uint32_t a;
    asm("{ .reg .u64 t; cvta.to.shared.u64 t, %1; cvt.u32.u64 %0, t; }" : "=r"(a) : "l"(p));
    return a;
}

__device__ __forceinline__ void ldmx4t(uint32_t* r, uint32_t addr) {
    asm volatile("ldmatrix.sync.aligned.m8n8.x4.trans.shared.b16 {%0,%1,%2,%3}, [%4];"
                 : "=r"(r[0]), "=r"(r[1]), "=r"(r[2]), "=r"(r[3]) : "r"(addr));
}

__device__ __forceinline__ void mma16816(float* d, const uint32_t* a, uint32_t b0, uint32_t b1) {
    asm volatile("mma.sync.aligned.m16n8k16.row.col.f32.f16.f16.f32 "
                 "{%0,%1,%2,%3}, {%4,%5,%6,%7}, {%8,%9}, {%0,%1,%2,%3};"
                 : "+f"(d[0]), "+f"(d[1]), "+f"(d[2]), "+f"(d[3])
                 : "r"(a[0]), "r"(a[1]), "r"(a[2]), "r"(a[3]), "r"(b0), "r"(b1));
}

__global__ void k_prep(const float* __restrict__ wpw) {
    int t = threadIdx.x;
    if (t < KTOT) { g_sum[t] = 0.f; g_sq[t] = 0.f; }
    if (t < DIMC) { g_osum[t] = 0.f; g_osq[t] = 0.f; }
    for (int idx = t; idx < 64 * KTOT; idx += 256) {
        int k = idx >> 6, n = idx & 63;
        g_wh[idx] = __float2half(wpw[n * KTOT + k]);
    }
}

// Fused 3-branch depthwise conv (+bias) + fp32 stats, fp16 scratch stores.
// Thread computes an h-pair (rows h, h+1) x 4 w; interior fast path skips predicates.
__global__ void __launch_bounds__(128) k_conv(
    const float* __restrict__ x,
    const float* __restrict__ wd, const float* __restrict__ bd,
    const float* __restrict__ wh, const float* __restrict__ bh,
    const float* __restrict__ wv, const float* __restrict__ bw)
{
    const int d = blockIdx.x;
    const int c = blockIdx.y;

    float Wd[9], Wh[9], Wv[9];
    #pragma unroll
    for (int i = 0; i < 9; i++) {
        Wd[i] = wd[c * 9 + i];
        Wh[i] = wh[c * 9 + i];
        Wv[i] = wv[c * 9 + i];
    }
    const float bdv = bd[c], bhv = bh[c], bwv = bw[c];

    const float* pc = x + (size_t)c * NSP + (size_t)d * HW_;
    const float* pm = pc - HW_;
    const float* pq = pc + HW_;
    const bool dm = d > 0, dp = d < D_ - 1;
    const bool dint = dm && dp;

    __half* od = g_scrh + (size_t)c * NSP + (size_t)d * HW_;
    __half* oh = od + (size_t)DIMC * NSP;
    __half* ow = oh + (size_t)DIMC * NSP;

    float s0 = 0.f, q0 = 0.f, s1 = 0.f, q1 = 0.f, s2 = 0.f, q2 = 0.f;

    for (int it = threadIdx.x; it < (HW_ >> 3); it += 128) {
        const int h = (it >> 5) * 2;
        const int w4 = (it & 31) << 2;
        const bool wl = w4 > 0, wr = w4 < W_ - 4;
        const bool vhm = h > 0;
        const bool vhp2 = (h + 2) < H_;

        float pc6[4][6];
        float pm6a[6], pm6b[6], pm4a[4], pm4b[4];
        float pq6a[6], pq6b[6], pq4a[4], pq4b[4];

        if (dint && vhm && vhp2 && wl && wr) {
            // interior fast path: unpredicated loads
            auto ld6u = [&](float* a, const float* row) {
                float4 f = *reinterpret_cast<const float4*>(row + w4);
                a[1] = f.x; a[2] = f.y; a[3] = f.z; a[4] = f.w;
                a[0] = row[w4 - 1];
                a[5] = row[w4 + 4];
            };
            auto ld4u = [&](float* a, const float* row) {
                float4 f = *reinterpret_cast<const float4*>(row + w4);
                a[0] = f.x; a[1] = f.y; a[2] = f.z; a[3] = f.w;
            };
            ld6u(pc6[0], pc + (h - 1) * W_);
            ld6u(pc6[1], pc + h * W_);
            ld6u(pc6[2], pc + (h + 1) * W_);
            ld6u(pc6[3], pc + (h + 2) * W_);
            ld6u(pm6a, pm + h * W_);
            ld6u(pm6b, pm + (h + 1) * W_);
            ld4u(pm4a, pm + (h - 1) * W_);
            ld4u(pm4b, pm + (h + 2) * W_);
            ld6u(pq6a, pq + h * W_);
            ld6u(pq6b, pq + (h + 1) * W_);
            ld4u(pq4a, pq + (h - 1) * W_);
            ld4u(pq4b, pq + (h + 2) * W_);
        } else {
            auto ld6 = [&](float* a, const float* row, bool valid) {
                if (valid) {
                    float4 f = *reinterpret_cast<const float4*>(row + w4);
                    a[1] = f.x; a[2] = f.y; a[3] = f.z; a[4] = f.w;
                    a[0] = wl ? row[w4 - 1] : 0.f;
                    a[5] = wr ? row[w4 + 4] : 0.f;
                } else {
                    a[0] = a[1] = a[2] = a[3] = a[4] = a[5] = 0.f;
                }
            };
            auto ld4 = [&](float* a, const float* row, bool valid) {
                if (valid) {
                    float4 f = *reinterpret_cast<const float4*>(row + w4);
                    a[0] = f.x; a[1] = f.y; a[2] = f.z; a[3] = f.w;
                } else {
                    a[0] = a[1] = a[2] = a[3] = 0.f;
                }
            };
            ld6(pc6[0], pc + (h - 1) * W_, vhm);
            ld6(pc6[1], pc + h * W_, true);
            ld6(pc6[2], pc + (h + 1) * W_, true);
            ld6(pc6[3], pc + (h + 2) * W_, vhp2);
            ld6(pm6a, pm + h * W_, dm);
            ld6(pm6b, pm + (h + 1) * W_, dm);
            ld4(pm4a, pm + (h - 1) * W_, dm && vhm);
            ld4(pm4b, pm + (h + 2) * W_, dm && vhp2);
            ld6(pq6a, pq + h * W_, dp);
            ld6(pq6b, pq + (h + 1) * W_, dp);
            ld4(pq4a, pq + (h - 1) * W_, dp && vhm);
            ld4(pq4b, pq + (h + 2) * W_, dp && vhp2);
        }

        auto comp = [&](const float (&cm)[6], const float (&cc6)[6], const float (&cp)[6],
                        const float (&mm6)[6], const float (&pp6)[6],
                        const float (&mhm)[4], const float (&mhp)[4],
                        const float (&phm)[4], const float (&php)[4], int idx) {
            float rd[4], rh[4], rw[4];
            #pragma unroll
            for (int i = 0; i < 4; i++) {
                float vd = bdv;
                vd = fmaf(Wd[0], cm[i], vd);  vd = fmaf(Wd[1], cm[i+1], vd);  vd = fmaf(Wd[2], cm[i+2], vd);
                vd = fmaf(Wd[3], cc6[i], vd); vd = fmaf(Wd[4], cc6[i+1], vd); vd = fmaf(Wd[5], cc6[i+2], vd);
                vd = fmaf(Wd[6], cp[i], vd);  vd = fmaf(Wd[7], cp[i+1], vd);  vd = fmaf(Wd[8], cp[i+2], vd);

                float vh = bhv;
                vh = fmaf(Wh[0], mm6[i], vh); vh = fmaf(Wh[1], mm6[i+1], vh); vh = fmaf(Wh[2], mm6[i+2], vh);
                vh = fmaf(Wh[3], cc6[i], vh); vh = fmaf(Wh[4], cc6[i+1], vh); vh = fmaf(Wh[5], cc6[i+2], vh);
                vh = fmaf(Wh[6], pp6[i], vh); vh = fmaf(Wh[7], pp6[i+1], vh); vh = fmaf(Wh[8], pp6[i+2], vh);

                float vw = bwv;
                vw = fmaf(Wv[0], mhm[i], vw);   vw = fmaf(Wv[1], mm6[i+1], vw); vw = fmaf(Wv[2], mhp[i], vw);
                vw = fmaf(Wv[3], cm[i+1], vw);  vw = fmaf(Wv[4], cc6[i+1], vw); vw = fmaf(Wv[5], cp[i+1], vw);
                vw = fmaf(Wv[6], phm[i], vw);   vw = fmaf(Wv[7], pp6[i+1], vw); vw = fmaf(Wv[8], php[i], vw);

                rd[i] = vd; rh[i] = vh; rw[i] = vw;
                s0 += vd; q0 = fmaf(vd, vd, q0);
                s1 += vh; q1 = fmaf(vh, vh, q1);
                s2 += vw; q2 = fmaf(vw, vw, q2);
            }
            __half2 a0 = __floats2half2_rn(rd[0], rd[1]);
            __half2 a1 = __floats2half2_rn(rd[2], rd[3]);
            __half2 b0 = __floats2half2_rn(rh[0], rh[1]);
            __half2 b1 = __floats2half2_rn(rh[2], rh[3]);
            __half2 c0 = __floats2half2_rn(rw[0], rw[1]);
            __half2 c1 = __floats2half2_rn(rw[2], rw[3]);
            *reinterpret_cast<uint2*>(od + idx) =
                make_uint2(*reinterpret_cast<unsigned*>(&a0), *reinterpret_cast<unsigned*>(&a1));
            *reinterpret_cast<uint2*>(oh + idx) =
                make_uint2(*reinterpret_cast<unsigned*>(&b0), *reinterpret_cast<unsigned*>(&b1));
            *reinterpret_cast<uint2*>(ow + idx) =
                make_uint2(*reinterpret_cast<unsigned*>(&c0), *reinterpret_cast<unsigned*>(&c1));
        };

        float mhpA[4] = { pm6b[1], pm6b[2], pm6b[3], pm6b[4] };
        float phpA[4] = { pq6b[1], pq6b[2], pq6b[3], pq6b[4] };
        float mhmB[4] = { pm6a[1], pm6a[2], pm6a[3], pm6a[4] };
        float phmB[4] = { pq6a[1], pq6a[2], pq6a[3], pq6a[4] };

        comp(pc6[0], pc6[1], pc6[2], pm6a, pq6a, pm4a, mhpA, pq4a, phpA, h * W_ + w4);
        comp(pc6[1], pc6[2], pc6[3], pm6b, pq6b, mhmB, pm4b, phmB, pq4b, (h + 1) * W_ + w4);
    }

    s0 = warp_red(s0); q0 = warp_red(q0);
    s1 = warp_red(s1); q1 = warp_red(q1);
    s2 = warp_red(s2); q2 = warp_red(q2);
    if ((threadIdx.x & 31) == 0) {
        atomicAdd(&g_sum[c], s0);             atomicAdd(&g_sq[c], q0);
        atomicAdd(&g_sum[DIMC + c], s1);      atomicAdd(&g_sq[DIMC + c], q1);
        atomicAdd(&g_sum[2 * DIMC + c], s2);  atomicAdd(&g_sq[2 * DIMC + c], q2);
    }
}

__global__ void k_stats() {
    int k = threadIdx.x;
    if (k >= KTOT) return;
    const float n = (float)NSP;
    float mean = g_sum[k] / n;
    float var = g_sq[k] / n - mean * mean;
    float sc = rsqrtf(var + EPS_);
    g_sb[k] = make_float2(sc, -mean * sc);
}

// ---------- mma.sync pointwise GEMM (round-12 config: measured 213 us) ----------
// 256 threads (8 warps = 4 m-groups x 2 n-halves). M=128, N=64, K=192 resident.
// Swizzled A (256B rows, 48KB) + B (128B rows, 24KB) = 72KB -> 3 CTAs/SM.
constexpr int PW_SM_B = 0;                       // 192 * 128 = 24576
constexpr int PW_SM_A = 24576;                   // 192 * 256 = 49152 (reused: staging)
constexpr int PW_SM_TOTAL = 73728;               // 9 x 8KB
constexpr int STG_STRIDE = 136;                  // halves per channel row in staging

__device__ __forceinline__ int a_off(int k, int byte) {
    return PW_SM_A + k * 256 + (byte ^ ((k & 7) << 4));
}
__device__ __forceinline__ int b_off(int k, int byte) {
    return PW_SM_B + k * 128 + (byte ^ ((k & 7) << 4));
}

__global__ void __launch_bounds__(256, 3) k_pw_mma() {
    extern __shared__ char smem[];
    const uint32_t sa = smem_to_u32(smem);
    const int tid = threadIdx.x;
    const int wid = tid >> 5;
    const int lid = tid & 31;
    const size_t base = (size_t)blockIdx.x * 128;

    // B fill: 192 rows x 128B, swizzled 16B chunks
    {
        const uint4* src = reinterpret_cast<const uint4*>(g_wh);
        for (int i = tid; i < KTOT * 8; i += 256) {
            int row = i >> 3, part = i & 7;
            *reinterpret_cast<uint4*>(smem + b_off(row, part * 16)) = src[i];
        }
    }
    __syncthreads();

    // A fill: normalize+lrelu fp16 scratch into swizzled rows
    #pragma unroll
    for (int it = 0; it < 12; it++) {
        const int idx = it * 256 + tid;
        const int g = idx & 15;
        const int k = idx >> 4;
        uint4 raw = *reinterpret_cast<const uint4*>(g_scrh + (size_t)k * NSP + base + g * 8);
        float2 s = __ldg(&g_sb[k]);
        const __half2* hp = reinterpret_cast<const __half2*>(&raw);
        uint4 outv;
        uint32_t* ov = reinterpret_cast<uint32_t*>(&outv);
        #pragma unroll
        for (int q = 0; q < 4; q++) {
            float2 f = __half22float2(hp[q]);
            float v0 = fmaf(f.x, s.x, s.y); v0 = fmaxf(v0, SLOPE_ * v0);
            float v1 = fmaf(f.y, s.x, s.y); v1 = fmaxf(v1, SLOPE_ * v1);
            __half2 h = __floats2half2_rn(v0, v1);
            ov[q] = *reinterpret_cast<uint32_t*>(&h);
        }
        *reinterpret_cast<uint4*>(smem + a_off(k, g * 16)) = outv;
    }
    __syncthreads();

    const int m0 = (wid & 3) * 32;
    const int nh = (wid >> 2) * 32;

    float acc[2][4][4];
    #pragma unroll
    for (int mt = 0; mt < 2; mt++)
        #pragma unroll
        for (int nt = 0; nt < 4; nt++)
            #pragma unroll
            for (int e = 0; e < 4; e++) acc[mt][nt][e] = 0.f;

    const int a_k = (lid & 7) | ((lid & 16) >> 1);
    const int a_m = (lid & 8);
    const int b_k = lid & 15;
    const int b_n = (lid >> 4) * 8;

    #pragma unroll
    for (int ks = 0; ks < 12; ks++) {
        const int k0 = ks * 16;
        uint32_t af[2][4];
        #pragma unroll
        for (int mt = 0; mt < 2; mt++)
            ldmx4t(af[mt], sa + a_off(k0 + a_k, (m0 + mt * 16 + a_m) * 2));
        uint32_t bf[2][4];
        #pragma unroll
        for (int nb = 0; nb < 2; nb++)
            ldmx4t(bf[nb], sa + b_off(k0 + b_k, (nh + nb * 16 + b_n) * 2));
        #pragma unroll
        for (int mt = 0; mt < 2; mt++)
            #pragma unroll
            for (int nb = 0; nb < 2; nb++) {
                mma16816(acc[mt][2 * nb],     af[mt], bf[nb][0], bf[nb][1]);
                mma16816(acc[mt][2 * nb + 1], af[mt], bf[nb][2], bf[nb][3]);
            }
    }
    __syncthreads();  // everyone done with A and B regions

    // reduction buffer lives in the dead B region
    float* red = reinterpret_cast<float*>(smem + PW_SM_B);
    if (tid < 128) red[tid] = 0.f;
    __syncthreads();

    const int r_lo = (lid >> 2);
    const int c_off = (lid & 3) * 2;
    float sc0[4], qc0[4], sc1[4], qc1[4];
    #pragma unroll
    for (int nt = 0; nt < 4; nt++) { sc0[nt] = qc0[nt] = sc1[nt] = qc1[nt] = 0.f; }
    #pragma unroll
    for (int mt = 0; mt < 2; mt++)
        #pragma unroll
        for (int nt = 0; nt < 4; nt++) {
            float d0 = acc[mt][nt][0], d1 = acc[mt][nt][1];
            float d2 = acc[mt][nt][2], d3 = acc[mt][nt][3];
            sc0[nt] += d0 + d2; qc0[nt] += d0 * d0 + d2 * d2;
            sc1[nt] += d1 + d3; qc1[nt] += d1 * d1 + d3 * d3;
        }
    #pragma unroll
    for (int o = 4; o <= 16; o <<= 1) {
        #pragma unroll
        for (int nt = 0; nt < 4; nt++) {
            sc0[nt] += __shfl_xor_sync(0xffffffffu, sc0[nt], o);
            qc0[nt] += __shfl_xor_sync(0xffffffffu, qc0[nt], o);
            sc1[nt] += __shfl_xor_sync(0xffffffffu, sc1[nt], o);
            qc1[nt] += __shfl_xor_sync(0xffffffffu, qc1[nt], o);
        }
    }
    if (lid < 4) {
        #pragma unroll
        for (int nt = 0; nt < 4; nt++) {
            const int c0 = nh + nt * 8 + c_off;
            atomicAdd(&red[c0], sc0[nt]);
            atomicAdd(&red[64 + c0], qc0[nt]);
            atomicAdd(&red[c0 + 1], sc1[nt]);
            atomicAdd(&red[64 + c0 + 1], qc1[nt]);
        }
    }

    // stage accumulators (fp16) into the dead A region
    __half* stg = reinterpret_cast<__half*>(smem + PW_SM_A);
    #pragma unroll
    for (int mt = 0; mt < 2; mt++) {
        const int row = m0 + mt * 16 + r_lo;
        #pragma unroll
        for (int nt = 0; nt < 4; nt++) {
            const int c0 = nh + nt * 8 + c_off;
            stg[c0 * STG_STRIDE + row]           = __float2half(acc[mt][nt][0]);
            stg[(c0 + 1) * STG_STRIDE + row]     = __float2half(acc[mt][nt][1]);
            stg[c0 * STG_STRIDE + row + 8]       = __float2half(acc[mt][nt][2]);
            stg[(c0 + 1) * STG_STRIDE + row + 8] = __float2half(acc[mt][nt][3]);
        }
    }
    __syncthreads();

    if (tid < 64) atomicAdd(&g_osum[tid], red[tid]);
    else if (tid < 128) atomicAdd(&g_osq[tid - 64], red[tid]);

    {
        const int c = tid >> 2;
        const int seg = (tid & 3) * 32;
        const uint4* src = reinterpret_cast<const uint4*>(stg + c * STG_STRIDE + seg);
        uint4* dst = reinterpret_cast<uint4*>(g_outh + (size_t)c * NSP + base + seg);
        #pragma unroll
        for (int i = 0; i < 4; i++) dst[i] = src[i];
    }
}

__global__ void k_ofin() {
    int c = threadIdx.x;
    if (c >= DIMC) return;
    const float n = (float)NSP;
    float mean = g_osum[c] / n;
    float var = g_osq[c] / n - mean * mean;
    float sc = rsqrtf(var + EPS_);
    g_oscale[c] = sc;
    g_obias[c] = -mean * sc;
}

__global__ void __launch_bounds__(256) k_onorm(float* __restrict__ out) {
    const int c = blockIdx.y;
    const size_t pos = ((size_t)blockIdx.x * 256 + threadIdx.x) * 8;
    uint4 raw = *reinterpret_cast<const uint4*>(g_outh + (size_t)c * NSP + pos);
    const float sc = g_oscale[c], bi = g_obias[c];
    const __half2* hp = reinterpret_cast<const __half2*>(&raw);
    float o[8];
    #pragma unroll
    for (int q = 0; q < 4; q++) {
        float2 f = __half22float2(hp[q]);
        float v0 = fmaf(f.x, sc, bi); v0 = fmaxf(v0, SLOPE_ * v0);
        float v1 = fmaf(f.y, sc, bi); v1 = fmaxf(v1, SLOPE_ * v1);
        o[2 * q] = v0; o[2 * q + 1] = v1;
    }
    float4* dst = reinterpret_cast<float4*>(out + (size_t)c * NSP + pos);
    dst[0] = make_float4(o[0], o[1], o[2], o[3]);
    dst[1] = make_float4(o[4], o[5], o[6], o[7]);
}

extern "C" void kernel_launch(void* const* d_in, const int* in_sizes, int n_in,
                              void* d_out, int out_size) {
    const float* x   = (const float*)d_in[0];
    const float* wd  = (const float*)d_in[1];
    const float* bd  = (const float*)d_in[2];
    const float* wh  = (const float*)d_in[3];
    const float* bh  = (const float*)d_in[4];
    const float* wv  = (const float*)d_in[5];
    const float* bw  = (const float*)d_in[6];
    const float* wpw = (const float*)d_in[7];
    // d_in[8] = pointwise bias: dropped (cancels exactly in the output InstanceNorm)
    float* out = (float*)d_out;

    cudaFuncSetAttribute(k_pw_mma, cudaFuncAttributeMaxDynamicSharedMemorySize, PW_SM_TOTAL);

    k_prep<<<1, 256>>>(wpw);
    k_conv<<<dim3(D_, DIMC), 128>>>(x, wd, bd, wh, bh, wv, bw);
    k_stats<<<1, KTOT>>>();
    k_pw_mma<<<(unsigned)(NSP / 128), 256, PW_SM_TOTAL>>>();
    k_ofin<<<1, DIMC>>>();
    k_onorm<<<dim3((unsigned)(NSP / 2048), DIMC), 256>>>(out);
}

// round 16
// speedup vs baseline: 1.1318x; 1.1216x over previous
#include <cuda_runtime.h>
#include <cuda_fp16.h>
#include <cstdint>

constexpr int DIMC = 64;
constexpr int D_ = 64, H_ = 128, W_ = 128;
constexpr int HW_ = H_ * W_;
constexpr size_t NSP = (size_t)D_ * HW_;
constexpr int KTOT = 3 * DIMC;
constexpr float EPS_ = 1e-5f;
constexpr float SLOPE_ = 0.01f;

__device__ __align__(16) __half g_scrh[(size_t)KTOT * NSP];   // 384 MB branch scratch [k][spatial]
__device__ __align__(16) __half g_outh[(size_t)DIMC * NSP];   // 128 MB pre-norm output [c][spatial]
__device__ __align__(16) __half g_wh[KTOT * 64];              // fp16 weights [k][n]
__device__ float g_sum[KTOT];
__device__ float g_sq[KTOT];
__device__ __align__(8) float2 g_sb[KTOT];                    // packed (scale, bias)
__device__ float g_osum[DIMC];
__device__ float g_osq[DIMC];

__device__ __forceinline__ float warp_red(float v) {
    #pragma unroll
    for (int o = 16; o > 0; o >>= 1) v += __shfl_down_sync(0xffffffffu, v, o);
    return v;
}

__device__ __forceinline__ uint32_t smem_to_u32(const void* p) {
    uint32_t a;
    asm("{ .reg .u64 t; cvta.to.shared.u64 t, %1; cvt.u32.u64 %0, t; }" : "=r"(a) : "l"(p));
    return a;
}

__device__ __forceinline__ void ldmx4t(uint32_t* r, uint32_t addr) {
    asm volatile("ldmatrix.sync.aligned.m8n8.x4.trans.shared.b16 {%0,%1,%2,%3}, [%4];"
                 : "=r"(r[0]), "=r"(r[1]), "=r"(r[2]), "=r"(r[3]) : "r"(addr));
}

__device__ __forceinline__ void mma16816(float* d, const uint32_t* a, uint32_t b0, uint32_t b1) {
    asm volatile("mma.sync.aligned.m16n8k16.row.col.f32.f16.f16.f32 "
                 "{%0,%1,%2,%3}, {%4,%5,%6,%7}, {%8,%9}, {%0,%1,%2,%3};"
                 : "+f"(d[0]), "+f"(d[1]), "+f"(d[2]), "+f"(d[3])
                 : "r"(a[0]), "r"(a[1]), "r"(a[2]), "r"(a[3]), "r"(b0), "r"(b1));
}

__global__ void k_prep(const float* __restrict__ wpw) {
    int t = threadIdx.x;
    if (t < KTOT) { g_sum[t] = 0.f; g_sq[t] = 0.f; }
    if (t < DIMC) { g_osum[t] = 0.f; g_osq[t] = 0.f; }
    for (int idx = t; idx < 64 * KTOT; idx += 256) {
        int k = idx >> 6, n = idx & 63;
        g_wh[idx] = __float2half(wpw[n * KTOT + k]);
    }
}

// Fused 3-branch depthwise conv (+bias) + fp32 stats, fp16 scratch stores.
// Thread = h-pair x 4 w. A warp spans one full row, so w-halos come from
// neighbor lanes via shfl instead of extra scalar LDGs (28 -> 12 LDG/iter).
__global__ void __launch_bounds__(128) k_conv(
    const float* __restrict__ x,
    const float* __restrict__ wd, const float* __restrict__ bd,
    const float* __restrict__ wh, const float* __restrict__ bh,
    const float* __restrict__ wv, const float* __restrict__ bw)
{
    const int d = blockIdx.x;
    const int c = blockIdx.y;
    const int lane = threadIdx.x & 31;

    float Wd[9], Wh[9], Wv[9];
    #pragma unroll
    for (int i = 0; i < 9; i++) {
        Wd[i] = wd[c * 9 + i];
        Wh[i] = wh[c * 9 + i];
        Wv[i] = wv[c * 9 + i];
    }
    const float bdv = bd[c], bhv = bh[c], bwv = bw[c];

    const float* pc = x + (size_t)c * NSP + (size_t)d * HW_;
    const float* pm = pc - HW_;
    const float* pq = pc + HW_;
    const bool dm = d > 0, dp = d < D_ - 1;

    __half* od = g_scrh + (size_t)c * NSP + (size_t)d * HW_;
    __half* oh = od + (size_t)DIMC * NSP;
    __half* ow = oh + (size_t)DIMC * NSP;

    float s0 = 0.f, q0 = 0.f, s1 = 0.f, q1 = 0.f, s2 = 0.f, q2 = 0.f;

    for (int it = threadIdx.x; it < (HW_ >> 3); it += 128) {
        const int h = (it >> 5) * 2;
        const int w4 = (it & 31) << 2;   // == lane * 4 within the warp's row
        const bool vhm = h > 0;          // warp-uniform
        const bool vhp2 = (h + 2) < H_;  // warp-uniform

        // ld6: one float4 + halos from neighbor lanes (warp boundary == row edge)
        auto ld6 = [&](float* a, const float* row, bool valid) {
            float4 f = make_float4(0.f, 0.f, 0.f, 0.f);
            if (valid) f = *reinterpret_cast<const float4*>(row + w4);
            float lft = __shfl_up_sync(0xffffffffu, f.w, 1);
            float rgt = __shfl_down_sync(0xffffffffu, f.x, 1);
            a[0] = (lane == 0) ? 0.f : lft;
            a[5] = (lane == 31) ? 0.f : rgt;
            a[1] = f.x; a[2] = f.y; a[3] = f.z; a[4] = f.w;
        };
        auto ld4 = [&](float* a, const float* row, bool valid) {
            float4 f = make_float4(0.f, 0.f, 0.f, 0.f);
            if (valid) f = *reinterpret_cast<const float4*>(row + w4);
            a[0] = f.x; a[1] = f.y; a[2] = f.z; a[3] = f.w;
        };

        float pc6[4][6];
        ld6(pc6[0], pc + (h - 1) * W_, vhm);
        ld6(pc6[1], pc + h * W_, true);
        ld6(pc6[2], pc + (h + 1) * W_, true);
        ld6(pc6[3], pc + (h + 2) * W_, vhp2);
        float pm6a[6], pm6b[6], pm4a[4], pm4b[4];
        ld6(pm6a, pm + h * W_, dm);
        ld6(pm6b, pm + (h + 1) * W_, dm);
        ld4(pm4a, pm + (h - 1) * W_, dm && vhm);
        ld4(pm4b, pm + (h + 2) * W_, dm && vhp2);
        float pq6a[6], pq6b[6], pq4a[4], pq4b[4];
        ld6(pq6a, pq + h * W_, dp);
        ld6(pq6b, pq + (h + 1) * W_, dp);
        ld4(pq4a, pq + (h - 1) * W_, dp && vhm);
        ld4(pq4b, pq + (h + 2) * W_, dp && vhp2);

        auto comp = [&](const float (&cm)[6], const float (&cc6)[6], const float (&cp)[6],
                        const float (&mm6)[6], const float (&pp6)[6],
                        const float (&mhm)[4], const float (&mhp)[4],
                        const float (&phm)[4], const float (&php)[4], int idx) {
            float rd[4], rh[4], rw[4];
            #pragma unroll
            for (int i = 0; i < 4; i++) {
                float vd = bdv;
                vd = fmaf(Wd[0], cm[i], vd);  vd = fmaf(Wd[1], cm[i+1], vd);  vd = fmaf(Wd[2], cm[i+2], vd);
                vd = fmaf(Wd[3], cc6[i], vd); vd = fmaf(Wd[4], cc6[i+1], vd); vd = fmaf(Wd[5], cc6[i+2], vd);
                vd = fmaf(Wd[6], cp[i], vd);  vd = fmaf(Wd[7], cp[i+1], vd);  vd = fmaf(Wd[8], cp[i+2], vd);

                float vh = bhv;
                vh = fmaf(Wh[0], mm6[i], vh); vh = fmaf(Wh[1], mm6[i+1], vh); vh = fmaf(Wh[2], mm6[i+2], vh);
                vh = fmaf(Wh[3], cc6[i], vh); vh = fmaf(Wh[4], cc6[i+1], vh); vh = fmaf(Wh[5], cc6[i+2], vh);
                vh = fmaf(Wh[6], pp6[i], vh); vh = fmaf(Wh[7], pp6[i+1], vh); vh = fmaf(Wh[8], pp6[i+2], vh);

                float vw = bwv;
                vw = fmaf(Wv[0], mhm[i], vw);   vw = fmaf(Wv[1], mm6[i+1], vw); vw = fmaf(Wv[2], mhp[i], vw);
                vw = fmaf(Wv[3], cm[i+1], vw);  vw = fmaf(Wv[4], cc6[i+1], vw); vw = fmaf(Wv[5], cp[i+1], vw);
                vw = fmaf(Wv[6], phm[i], vw);   vw = fmaf(Wv[7], pp6[i+1], vw); vw = fmaf(Wv[8], php[i], vw);

                rd[i] = vd; rh[i] = vh; rw[i] = vw;
                s0 += vd; q0 = fmaf(vd, vd, q0);
                s1 += vh; q1 = fmaf(vh, vh, q1);
                s2 += vw; q2 = fmaf(vw, vw, q2);
            }
            __half2 a0 = __floats2half2_rn(rd[0], rd[1]);
            __half2 a1 = __floats2half2_rn(rd[2], rd[3]);
            __half2 b0 = __floats2half2_rn(rh[0], rh[1]);
            __half2 b1 = __floats2half2_rn(rh[2], rh[3]);
            __half2 c0 = __floats2half2_rn(rw[0], rw[1]);
            __half2 c1 = __floats2half2_rn(rw[2], rw[3]);
            *reinterpret_cast<uint2*>(od + idx) =
                make_uint2(*reinterpret_cast<unsigned*>(&a0), *reinterpret_cast<unsigned*>(&a1));
            *reinterpret_cast<uint2*>(oh + idx) =
                make_uint2(*reinterpret_cast<unsigned*>(&b0), *reinterpret_cast<unsigned*>(&b1));
            *reinterpret_cast<uint2*>(ow + idx) =
                make_uint2(*reinterpret_cast<unsigned*>(&c0), *reinterpret_cast<unsigned*>(&c1));
        };

        float mhpA[4] = { pm6b[1], pm6b[2], pm6b[3], pm6b[4] };
        float phpA[4] = { pq6b[1], pq6b[2], pq6b[3], pq6b[4] };
        float mhmB[4] = { pm6a[1], pm6a[2], pm6a[3], pm6a[4] };
        float phmB[4] = { pq6a[1], pq6a[2], pq6a[3], pq6a[4] };

        comp(pc6[0], pc6[1], pc6[2], pm6a, pq6a, pm4a, mhpA, pq4a, phpA, h * W_ + w4);
        comp(pc6[1], pc6[2], pc6[3], pm6b, pq6b, mhmB, pm4b, phmB, pq4b, (h + 1) * W_ + w4);
    }

    s0 = warp_red(s0); q0 = warp_red(q0);
    s1 = warp_red(s1); q1 = warp_red(q1);
    s2 = warp_red(s2); q2 = warp_red(q2);
    if ((threadIdx.x & 31) == 0) {
        atomicAdd(&g_sum[c], s0);             atomicAdd(&g_sq[c], q0);
        atomicAdd(&g_sum[DIMC + c], s1);      atomicAdd(&g_sq[DIMC + c], q1);
        atomicAdd(&g_sum[2 * DIMC + c], s2);  atomicAdd(&g_sq[2 * DIMC + c], q2);
    }
}

__global__ void k_stats() {
    int k = threadIdx.x;
    if (k >= KTOT) return;
    const float n = (float)NSP;
    float mean = g_sum[k] / n;
    float var = g_sq[k] / n - mean * mean;
    float sc = rsqrtf(var + EPS_);
    g_sb[k] = make_float2(sc, -mean * sc);
}

// ---------- mma.sync pointwise GEMM (round-12 config: measured 212-213 us) ----------
constexpr int PW_SM_B = 0;                       // 192 * 128 = 24576
constexpr int PW_SM_A = 24576;                   // 192 * 256 = 49152 (reused: staging)
constexpr int PW_SM_TOTAL = 73728;               // 9 x 8KB -> 3 CTAs/SM
constexpr int STG_STRIDE = 136;

__device__ __forceinline__ int a_off(int k, int byte) {
    return PW_SM_A + k * 256 + (byte ^ ((k & 7) << 4));
}
__device__ __forceinline__ int b_off(int k, int byte) {
    return PW_SM_B + k * 128 + (byte ^ ((k & 7) << 4));
}

__global__ void __launch_bounds__(256, 3) k_pw_mma() {
    extern __shared__ char smem[];
    const uint32_t sa = smem_to_u32(smem);
    const int tid = threadIdx.x;
    const int wid = tid >> 5;
    const int lid = tid & 31;
    const size_t base = (size_t)blockIdx.x * 128;

    // B fill + A fill (disjoint regions -> single sync after both)
    {
        const uint4* src = reinterpret_cast<const uint4*>(g_wh);
        for (int i = tid; i < KTOT * 8; i += 256) {
            int row = i >> 3, part = i & 7;
            *reinterpret_cast<uint4*>(smem + b_off(row, part * 16)) = src[i];
        }
    }
    #pragma unroll
    for (int it = 0; it < 12; it++) {
        const int idx = it * 256 + tid;
        const int g = idx & 15;
        const int k = idx >> 4;
        uint4 raw = *reinterpret_cast<const uint4*>(g_scrh + (size_t)k * NSP + base + g * 8);
        float2 s = __ldg(&g_sb[k]);
        const __half2* hp = reinterpret_cast<const __half2*>(&raw);
        uint4 outv;
        uint32_t* ov = reinterpret_cast<uint32_t*>(&outv);
        #pragma unroll
        for (int q = 0; q < 4; q++) {
            float2 f = __half22float2(hp[q]);
            float v0 = fmaf(f.x, s.x, s.y); v0 = fmaxf(v0, SLOPE_ * v0);
            float v1 = fmaf(f.y, s.x, s.y); v1 = fmaxf(v1, SLOPE_ * v1);
            __half2 h = __floats2half2_rn(v0, v1);
            ov[q] = *reinterpret_cast<uint32_t*>(&h);
        }
        *reinterpret_cast<uint4*>(smem + a_off(k, g * 16)) = outv;
    }
    __syncthreads();

    const int m0 = (wid & 3) * 32;
    const int nh = (wid >> 2) * 32;

    float acc[2][4][4];
    #pragma unroll
    for (int mt = 0; mt < 2; mt++)
        #pragma unroll
        for (int nt = 0; nt < 4; nt++)
            #pragma unroll
            for (int e = 0; e < 4; e++) acc[mt][nt][e] = 0.f;

    const int a_k = (lid & 7) | ((lid & 16) >> 1);
    const int a_m = (lid & 8);
    const int b_k = lid & 15;
    const int b_n = (lid >> 4) * 8;

    #pragma unroll
    for (int ks = 0; ks < 12; ks++) {
        const int k0 = ks * 16;
        uint32_t af[2][4];
        #pragma unroll
        for (int mt = 0; mt < 2; mt++)
            ldmx4t(af[mt], sa + a_off(k0 + a_k, (m0 + mt * 16 + a_m) * 2));
        uint32_t bf[2][4];
        #pragma unroll
        for (int nb = 0; nb < 2; nb++)
            ldmx4t(bf[nb], sa + b_off(k0 + b_k, (nh + nb * 16 + b_n) * 2));
        #pragma unroll
        for (int mt = 0; mt < 2; mt++)
            #pragma unroll
            for (int nb = 0; nb < 2; nb++) {
                mma16816(acc[mt][2 * nb],     af[mt], bf[nb][0], bf[nb][1]);
                mma16816(acc[mt][2 * nb + 1], af[mt], bf[nb][2], bf[nb][3]);
            }
    }
    __syncthreads();  // everyone done with A and B regions

    float* red = reinterpret_cast<float*>(smem + PW_SM_B);
    if (tid < 128) red[tid] = 0.f;
    __syncthreads();

    const int r_lo = (lid >> 2);
    const int c_off = (lid & 3) * 2;
    float sc0[4], qc0[4], sc1[4], qc1[4];
    #pragma unroll
    for (int nt = 0; nt < 4; nt++) { sc0[nt] = qc0[nt] = sc1[nt] = qc1[nt] = 0.f; }
    #pragma unroll
    for (int mt = 0; mt < 2; mt++)
        #pragma unroll
        for (int nt = 0; nt < 4; nt++) {
            float d0 = acc[mt][nt][0], d1 = acc[mt][nt][1];
            float d2 = acc[mt][nt][2], d3 = acc[mt][nt][3];
            sc0[nt] += d0 + d2; qc0[nt] += d0 * d0 + d2 * d2;
            sc1[nt] += d1 + d3; qc1[nt] += d1 * d1 + d3 * d3;
        }
    #pragma unroll
    for (int o = 4; o <= 16; o <<= 1) {
        #pragma unroll
        for (int nt = 0; nt < 4; nt++) {
            sc0[nt] += __shfl_xor_sync(0xffffffffu, sc0[nt], o);
            qc0[nt] += __shfl_xor_sync(0xffffffffu, qc0[nt], o);
            sc1[nt] += __shfl_xor_sync(0xffffffffu, sc1[nt], o);
            qc1[nt] += __shfl_xor_sync(0xffffffffu, qc1[nt], o);
        }
    }
    if (lid < 4) {
        #pragma unroll
        for (int nt = 0; nt < 4; nt++) {
            const int c0 = nh + nt * 8 + c_off;
            atomicAdd(&red[c0], sc0[nt]);
            atomicAdd(&red[64 + c0], qc0[nt]);
            atomicAdd(&red[c0 + 1], sc1[nt]);
            atomicAdd(&red[64 + c0 + 1], qc1[nt]);
        }
    }

    __half* stg = reinterpret_cast<__half*>(smem + PW_SM_A);
    #pragma unroll
    for (int mt = 0; mt < 2; mt++) {
        const int row = m0 + mt * 16 + r_lo;
        #pragma unroll
        for (int nt = 0; nt < 4; nt++) {
            const int c0 = nh + nt * 8 + c_off;
            stg[c0 * STG_STRIDE + row]           = __float2half(acc[mt][nt][0]);
            stg[(c0 + 1) * STG_STRIDE + row]     = __float2half(acc[mt][nt][1]);
            stg[c0 * STG_STRIDE + row + 8]       = __float2half(acc[mt][nt][2]);
            stg[(c0 + 1) * STG_STRIDE + row + 8] = __float2half(acc[mt][nt][3]);
        }
    }
    __syncthreads();

    if (tid < 64) atomicAdd(&g_osum[tid], red[tid]);
    else if (tid < 128) atomicAdd(&g_osq[tid - 64], red[tid]);

    {
        const int c = tid >> 2;
        const int seg = (tid & 3) * 32;
        const uint4* src = reinterpret_cast<const uint4*>(stg + c * STG_STRIDE + seg);
        uint4* dst = reinterpret_cast<uint4*>(g_outh + (size_t)c * NSP + base + seg);
        #pragma unroll
        for (int i = 0; i < 4; i++) dst[i] = src[i];
    }
}

// fp16 pre-norm -> normalized fp32 output; norm params computed inline
__global__ void __launch_bounds__(256) k_onorm(float* __restrict__ out) {
    const int c = blockIdx.y;
    const float n = (float)NSP;
    const float mean = g_osum[c] / n;
    const float var = g_osq[c] / n - mean * mean;
    const float sc = rsqrtf(var + EPS_);
    const float bi = -mean * sc;

    const size_t pos = ((size_t)blockIdx.x * 256 + threadIdx.x) * 8;
    uint4 raw = *reinterpret_cast<const uint4*>(g_outh + (size_t)c * NSP + pos);
    const __half2* hp = reinterpret_cast<const __half2*>(&raw);
    float o[8];
    #pragma unroll
    for (int q = 0; q < 4; q++) {
        float2 f = __half22float2(hp[q]);
        float v0 = fmaf(f.x, sc, bi); v0 = fmaxf(v0, SLOPE_ * v0);
        float v1 = fmaf(f.y, sc, bi); v1 = fmaxf(v1, SLOPE_ * v1);
        o[2 * q] = v0; o[2 * q + 1] = v1;
    }
    float4* dst = reinterpret_cast<float4*>(out + (size_t)c * NSP + pos);
    dst[0] = make_float4(o[0], o[1], o[2], o[3]);
    dst[1] = make_float4(o[4], o[5], o[6], o[7]);
}

extern "C" void kernel_launch(void* const* d_in, const int* in_sizes, int n_in,
                              void* d_out, int out_size) {
    const float* x   = (const float*)d_in[0];
    const float* wd  = (const float*)d_in[1];
    const float* bd  = (const float*)d_in[2];
    const float* wh  = (const float*)d_in[3];
    const float* bh  = (const float*)d_in[4];
    const float* wv  = (const float*)d_in[5];
    const float* bw  = (const float*)d_in[6];
    const float* wpw = (const float*)d_in[7];
    // d_in[8] = pointwise bias: dropped (cancels exactly in the output InstanceNorm)
    float* out = (float*)d_out;

    cudaFuncSetAttribute(k_pw_mma, cudaFuncAttributeMaxDynamicSharedMemorySize, PW_SM_TOTAL);

    k_prep<<<1, 256>>>(wpw);
    k_conv<<<dim3(D_, DIMC), 128>>>(x, wd, bd, wh, bh, wv, bw);
    k_stats<<<1, KTOT>>>();
    k_pw_mma<<<(unsigned)(NSP / 128), 256, PW_SM_TOTAL>>>();
    k_onorm<<<dim3((unsigned)(NSP / 2048), DIMC), 256>>>(out);
}